// round 7
// baseline (speedup 1.0000x reference)
#include <cuda_runtime.h>

// Problem constants
#define EMBED 2048
#define NHEAD 16
#define HDIM  128
#define BATCH 2
#define SEQ   2048
#define NTOK  (BATCH * SEQ)   // 4096

__device__ __constant__ float kScale = 0.022097086912079612f;  // 2048^-0.5

// Scratch (static __device__ globals: allocation-free per harness rules)
// Layout [3][b*16+h][t][hd]  (Q,K,V)
__device__ float g_QKV[3][(size_t)BATCH * NHEAD * SEQ * HDIM];
// Attention output in [b, t, d] layout (d = h*128 + hd), ready for the O-proj GEMM
__device__ float g_A[(size_t)NTOK * EMBED];

// ---------------------------------------------------------------------------
// SGEMM: C[4096 x 2048] = A[4096 x 2048] @ B[2048 x 2048] + bias
// 128x128 block tile, BK=8, 256 threads, 8x8 per thread.
// scatter=1: n-block == head; write to [b*16+h][t][hd] layout (for Q/K/V).
// scatter=0: plain row-major write.
// ---------------------------------------------------------------------------
__device__ __forceinline__ void sgemm_body(
    const float* __restrict__ A, const float* __restrict__ B,
    const float* __restrict__ bias, float* __restrict__ C, int scatter)
{
    __shared__ float As[8][132];   // transposed: As[k][m], padded
    __shared__ float Bs[8][128];   // Bs[k][n]

    const int tid = threadIdx.x;
    const int tr = tid >> 4;       // 0..15
    const int tc = tid & 15;       // 0..15
    const int m0 = blockIdx.y * 128;
    const int n0 = blockIdx.x * 128;

    float acc[8][8];
#pragma unroll
    for (int i = 0; i < 8; i++)
#pragma unroll
        for (int j = 0; j < 8; j++) acc[i][j] = 0.0f;

    const int a_row = tid >> 1;          // 0..127
    const int a_c   = (tid & 1) * 4;     // 0 or 4 within BK=8
    const int b_row = tid >> 5;          // 0..7
    const int b_c   = (tid & 31) * 4;    // 0..124

    const float* Ap = A + (size_t)(m0 + a_row) * EMBED + a_c;
    const float* Bp = B + (size_t)b_row * EMBED + n0 + b_c;

    for (int kt = 0; kt < EMBED / 8; kt++) {
        float4 av = *(const float4*)Ap;
        float4 bv = *(const float4*)Bp;
        __syncthreads();                 // previous tile's compute done
        As[a_c + 0][a_row] = av.x;
        As[a_c + 1][a_row] = av.y;
        As[a_c + 2][a_row] = av.z;
        As[a_c + 3][a_row] = av.w;
        *(float4*)&Bs[b_row][b_c] = bv;
        __syncthreads();

#pragma unroll
        for (int k = 0; k < 8; k++) {
            float4 a0 = *(const float4*)&As[k][tr * 4];
            float4 a1 = *(const float4*)&As[k][64 + tr * 4];
            float4 b0 = *(const float4*)&Bs[k][tc * 4];
            float4 b1 = *(const float4*)&Bs[k][64 + tc * 4];
            float ar[8] = {a0.x, a0.y, a0.z, a0.w, a1.x, a1.y, a1.z, a1.w};
            float br[8] = {b0.x, b0.y, b0.z, b0.w, b1.x, b1.y, b1.z, b1.w};
#pragma unroll
            for (int i = 0; i < 8; i++)
#pragma unroll
                for (int j = 0; j < 8; j++)
                    acc[i][j] = fmaf(ar[i], br[j], acc[i][j]);
        }
        Ap += 8;
        Bp += (size_t)8 * EMBED;
    }

    float4 bz0 = *(const float4*)(bias + n0 + tc * 4);
    float4 bz1 = *(const float4*)(bias + n0 + 64 + tc * 4);

#pragma unroll
    for (int i = 0; i < 8; i++) {
        const int row = (i < 4) ? (tr * 4 + i) : (64 + tr * 4 + (i - 4));
        float4 v0 = make_float4(acc[i][0] + bz0.x, acc[i][1] + bz0.y,
                                acc[i][2] + bz0.z, acc[i][3] + bz0.w);
        float4 v1 = make_float4(acc[i][4] + bz1.x, acc[i][5] + bz1.y,
                                acc[i][6] + bz1.z, acc[i][7] + bz1.w);
        if (scatter) {
            const int bb = m0 >> 11;              // batch index
            const int t  = (m0 & 2047) + row;     // position within sequence
            float* dst = C + ((size_t)(bb * NHEAD + blockIdx.x) * SEQ + t) * HDIM;
            *(float4*)(dst + tc * 4)      = v0;
            *(float4*)(dst + 64 + tc * 4) = v1;
        } else {
            float* dst = C + (size_t)(m0 + row) * EMBED + n0;
            *(float4*)(dst + tc * 4)      = v0;
            *(float4*)(dst + 64 + tc * 4) = v1;
        }
    }
}

__global__ __launch_bounds__(256, 2) void qkv_gemm_kernel(
    const float* __restrict__ x,
    const float* __restrict__ wq, const float* __restrict__ bq,
    const float* __restrict__ wk, const float* __restrict__ bk,
    const float* __restrict__ wv, const float* __restrict__ bv)
{
    const int z = blockIdx.z;
    const float* W  = (z == 0) ? wq : (z == 1) ? wk : wv;
    const float* Bi = (z == 0) ? bq : (z == 1) ? bk : bv;
    sgemm_body(x, W, Bi, g_QKV[z], 1);
}

__global__ __launch_bounds__(256, 2) void out_gemm_kernel(
    const float* __restrict__ wo, const float* __restrict__ bo,
    float* __restrict__ out)
{
    sgemm_body(g_A, wo, bo, out, 0);
}

// ---------------------------------------------------------------------------
// Flash attention, fp32. Block = 64 q-rows x one (b,h). 256 threads (16x16).
// Thread (ty,tx) owns S rows ty*4..+3 and S cols {tx, tx+16, tx+32, tx+48},
// and O cols tx*8..+7.
// K is stored in smem as XOR-swizzled float4 chunks (conflict-free loads).
// ---------------------------------------------------------------------------
#define QS_PITCH 132
// floats: Qs 64*132 + Ks 64*128 + Vs 64*128 + Ps 64*65
#define ATTN_SMEM_FLOATS (64 * QS_PITCH + 64 * 128 + 64 * 128 + 64 * 65)
#define ATTN_SMEM_BYTES  (ATTN_SMEM_FLOATS * 4)

__global__ __launch_bounds__(256) void attn_kernel()
{
    extern __shared__ float sm[];
    float*  Qs  = sm;                                  // [64][132]
    float4* Ks4 = (float4*)(sm + 64 * QS_PITCH);       // [64][32] swizzled
    float*  Vs  = sm + 64 * QS_PITCH + 64 * 128;       // [64][128]
    float*  Ps  = Vs + 64 * 128;                       // [64][65]

    const int tid = threadIdx.x;
    const int tx = tid & 15, ty = tid >> 4;
    const int bh = blockIdx.y;                         // b*16 + h
    const int q0 = blockIdx.x * 64;

    const float* Qb = g_QKV[0] + (size_t)bh * SEQ * HDIM;
    const float* Kb = g_QKV[1] + (size_t)bh * SEQ * HDIM;
    const float* Vb = g_QKV[2] + (size_t)bh * SEQ * HDIM;

    const float scale = kScale;

    // Load Q tile once, pre-scaled
#pragma unroll
    for (int i = 0; i < 8; i++) {
        int idx = tid + i * 256;
        int r = idx >> 5, c = (idx & 31) * 4;
        float4 v = *(const float4*)(Qb + (size_t)(q0 + r) * HDIM + c);
        float* d = Qs + r * QS_PITCH + c;
        d[0] = v.x * scale; d[1] = v.y * scale;
        d[2] = v.z * scale; d[3] = v.w * scale;
    }

    float m_r[4], l_r[4], O[4][8];
#pragma unroll
    for (int i = 0; i < 4; i++) {
        m_r[i] = -1e30f; l_r[i] = 0.0f;
#pragma unroll
        for (int c = 0; c < 8; c++) O[i][c] = 0.0f;
    }

    for (int kt = 0; kt < SEQ / 64; kt++) {
        __syncthreads();   // prev PV done (and Q store visible on iter 0)
        const int k0 = kt * 64;
#pragma unroll
        for (int i = 0; i < 8; i++) {
            int idx = tid + i * 256;
            int r = idx >> 5, c4 = idx & 31;
            float4 kv = *(const float4*)(Kb + (size_t)(k0 + r) * HDIM + c4 * 4);
            Ks4[r * 32 + (c4 ^ (r & 7))] = kv;         // swizzled store
            float4 vv = *(const float4*)(Vb + (size_t)(k0 + r) * HDIM + c4 * 4);
            *(float4*)(Vs + r * 128 + c4 * 4) = vv;
        }
        __syncthreads();

        // S = (Q*scale) @ K^T  (4x4 per thread)
        float s[4][4];
#pragma unroll
        for (int i = 0; i < 4; i++)
#pragma unroll
            for (int j = 0; j < 4; j++) s[i][j] = 0.0f;

#pragma unroll 4
        for (int kc = 0; kc < 32; kc++) {
            float4 q4[4], k4[4];
#pragma unroll
            for (int i = 0; i < 4; i++)
                q4[i] = *(const float4*)(Qs + (ty * 4 + i) * QS_PITCH + kc * 4);
#pragma unroll
            for (int j = 0; j < 4; j++) {
                int c = tx + 16 * j;
                k4[j] = Ks4[c * 32 + (kc ^ (c & 7))];  // swizzled load
            }
#pragma unroll
            for (int i = 0; i < 4; i++)
#pragma unroll
                for (int j = 0; j < 4; j++) {
                    s[i][j] = fmaf(q4[i].x, k4[j].x, s[i][j]);
                    s[i][j] = fmaf(q4[i].y, k4[j].y, s[i][j]);
                    s[i][j] = fmaf(q4[i].z, k4[j].z, s[i][j]);
                    s[i][j] = fmaf(q4[i].w, k4[j].w, s[i][j]);
                }
        }

        // Online softmax (row state replicated across the 16 tx lanes)
#pragma unroll
        for (int i = 0; i < 4; i++) {
            float mt = fmaxf(fmaxf(s[i][0], s[i][1]), fmaxf(s[i][2], s[i][3]));
#pragma unroll
            for (int o = 8; o > 0; o >>= 1)
                mt = fmaxf(mt, __shfl_xor_sync(0xffffffffu, mt, o));
            float mn = fmaxf(m_r[i], mt);
            float alpha = __expf(m_r[i] - mn);   // 0 on first tile (exp(-1e30))
            float ls = 0.0f;
#pragma unroll
            for (int j = 0; j < 4; j++) {
                float p = __expf(s[i][j] - mn);
                s[i][j] = p; ls += p;
            }
#pragma unroll
            for (int o = 8; o > 0; o >>= 1)
                ls += __shfl_xor_sync(0xffffffffu, ls, o);
            l_r[i] = l_r[i] * alpha + ls;
            m_r[i] = mn;
#pragma unroll
            for (int c = 0; c < 8; c++) O[i][c] *= alpha;
#pragma unroll
            for (int j = 0; j < 4; j++)
                Ps[(ty * 4 + i) * 65 + tx + 16 * j] = s[i][j];
        }
        __syncthreads();

        // O += P @ V
#pragma unroll 4
        for (int j = 0; j < 64; j++) {
            float4 v0 = *(const float4*)(Vs + j * 128 + tx * 8);
            float4 v1 = *(const float4*)(Vs + j * 128 + tx * 8 + 4);
#pragma unroll
            for (int i = 0; i < 4; i++) {
                float p = Ps[(ty * 4 + i) * 65 + j];
                O[i][0] = fmaf(p, v0.x, O[i][0]);
                O[i][1] = fmaf(p, v0.y, O[i][1]);
                O[i][2] = fmaf(p, v0.z, O[i][2]);
                O[i][3] = fmaf(p, v0.w, O[i][3]);
                O[i][4] = fmaf(p, v1.x, O[i][4]);
                O[i][5] = fmaf(p, v1.y, O[i][5]);
                O[i][6] = fmaf(p, v1.z, O[i][6]);
                O[i][7] = fmaf(p, v1.w, O[i][7]);
            }
        }
    }

    // Epilogue: normalize and write to [b, t, d] (d = h*128 + hd)
    const int b_ = bh >> 4, h_ = bh & 15;
#pragma unroll
    for (int i = 0; i < 4; i++) {
        float inv = 1.0f / l_r[i];
        int t = q0 + ty * 4 + i;
        float* dst = g_A + ((size_t)(b_ * SEQ + t)) * EMBED + h_ * HDIM + tx * 8;
        float4 o0 = make_float4(O[i][0] * inv, O[i][1] * inv,
                                O[i][2] * inv, O[i][3] * inv);
        float4 o1 = make_float4(O[i][4] * inv, O[i][5] * inv,
                                O[i][6] * inv, O[i][7] * inv);
        *(float4*)dst       = o0;
        *(float4*)(dst + 4) = o1;
    }
}

// ---------------------------------------------------------------------------
// Launch: QKV GEMMs (fused into one grid, z selects matrix) -> attention ->
// output projection. All on the default stream, graph-capturable, no allocs.
// ---------------------------------------------------------------------------
extern "C" void kernel_launch(void* const* d_in, const int* in_sizes, int n_in,
                              void* d_out, int out_size)
{
    (void)in_sizes; (void)n_in; (void)out_size;
    const float* x  = (const float*)d_in[0];
    const float* wq = (const float*)d_in[1];
    const float* bq = (const float*)d_in[2];
    const float* wk = (const float*)d_in[3];
    const float* bk = (const float*)d_in[4];
    const float* wv = (const float*)d_in[5];
    const float* bv = (const float*)d_in[6];
    const float* wo = (const float*)d_in[7];
    const float* bo = (const float*)d_in[8];
    float* out = (float*)d_out;

    // Opt-in to >48KB dynamic smem for the attention kernel (idempotent).
    cudaFuncSetAttribute(attn_kernel,
                         cudaFuncAttributeMaxDynamicSharedMemorySize,
                         ATTN_SMEM_BYTES);

    qkv_gemm_kernel<<<dim3(16, 32, 3), 256>>>(x, wq, bq, wk, bk, wv, bv);
    attn_kernel<<<dim3(32, 32), 256, ATTN_SMEM_BYTES>>>();
    out_gemm_kernel<<<dim3(16, 32), 256>>>(wo, bo, out);
}

// round 8
// speedup vs baseline: 1.0011x; 1.0011x over previous
#include <cuda_runtime.h>

// Problem constants
#define EMBED 2048
#define NHEAD 16
#define HDIM  128
#define BATCH 2
#define SEQ   2048
#define NTOK  (BATCH * SEQ)   // 4096

__device__ __constant__ float kScale = 0.022097086912079612f;  // 2048^-0.5

// Scratch (static __device__ globals: allocation-free per harness rules)
// Layout [3][b*16+h][t][hd]  (Q,K,V)
__device__ float g_QKV[3][(size_t)BATCH * NHEAD * SEQ * HDIM];
// Attention output in [b, t, d] layout (d = h*128 + hd), ready for the O-proj GEMM
__device__ float g_A[(size_t)NTOK * EMBED];

// ---------------------------------------------------------------------------
// SGEMM: C[4096 x 2048] = A[4096 x 2048] @ B[2048 x 2048] + bias
// 128x128 block tile, BK=8, 256 threads, 8x8 per thread.
// scatter=1: n-block == head; write to [b*16+h][t][hd] layout (for Q/K/V).
// scatter=0: plain row-major write.
// ---------------------------------------------------------------------------
__device__ __forceinline__ void sgemm_body(
    const float* __restrict__ A, const float* __restrict__ B,
    const float* __restrict__ bias, float* __restrict__ C, int scatter)
{
    __shared__ float As[8][132];   // transposed: As[k][m], padded
    __shared__ float Bs[8][128];   // Bs[k][n]

    const int tid = threadIdx.x;
    const int tr = tid >> 4;       // 0..15
    const int tc = tid & 15;       // 0..15
    const int m0 = blockIdx.y * 128;
    const int n0 = blockIdx.x * 128;

    float acc[8][8];
#pragma unroll
    for (int i = 0; i < 8; i++)
#pragma unroll
        for (int j = 0; j < 8; j++) acc[i][j] = 0.0f;

    const int a_row = tid >> 1;          // 0..127
    const int a_c   = (tid & 1) * 4;     // 0 or 4 within BK=8
    const int b_row = tid >> 5;          // 0..7
    const int b_c   = (tid & 31) * 4;    // 0..124

    const float* Ap = A + (size_t)(m0 + a_row) * EMBED + a_c;
    const float* Bp = B + (size_t)b_row * EMBED + n0 + b_c;

    for (int kt = 0; kt < EMBED / 8; kt++) {
        float4 av = *(const float4*)Ap;
        float4 bv = *(const float4*)Bp;
        __syncthreads();                 // previous tile's compute done
        As[a_c + 0][a_row] = av.x;
        As[a_c + 1][a_row] = av.y;
        As[a_c + 2][a_row] = av.z;
        As[a_c + 3][a_row] = av.w;
        *(float4*)&Bs[b_row][b_c] = bv;
        __syncthreads();

#pragma unroll
        for (int k = 0; k < 8; k++) {
            float4 a0 = *(const float4*)&As[k][tr * 4];
            float4 a1 = *(const float4*)&As[k][64 + tr * 4];
            float4 b0 = *(const float4*)&Bs[k][tc * 4];
            float4 b1 = *(const float4*)&Bs[k][64 + tc * 4];
            float ar[8] = {a0.x, a0.y, a0.z, a0.w, a1.x, a1.y, a1.z, a1.w};
            float br[8] = {b0.x, b0.y, b0.z, b0.w, b1.x, b1.y, b1.z, b1.w};
#pragma unroll
            for (int i = 0; i < 8; i++)
#pragma unroll
                for (int j = 0; j < 8; j++)
                    acc[i][j] = fmaf(ar[i], br[j], acc[i][j]);
        }
        Ap += 8;
        Bp += (size_t)8 * EMBED;
    }

    float4 bz0 = *(const float4*)(bias + n0 + tc * 4);
    float4 bz1 = *(const float4*)(bias + n0 + 64 + tc * 4);

#pragma unroll
    for (int i = 0; i < 8; i++) {
        const int row = (i < 4) ? (tr * 4 + i) : (64 + tr * 4 + (i - 4));
        float4 v0 = make_float4(acc[i][0] + bz0.x, acc[i][1] + bz0.y,
                                acc[i][2] + bz0.z, acc[i][3] + bz0.w);
        float4 v1 = make_float4(acc[i][4] + bz1.x, acc[i][5] + bz1.y,
                                acc[i][6] + bz1.z, acc[i][7] + bz1.w);
        if (scatter) {
            const int bb = m0 >> 11;              // batch index
            const int t  = (m0 & 2047) + row;     // position within sequence
            float* dst = C + ((size_t)(bb * NHEAD + blockIdx.x) * SEQ + t) * HDIM;
            *(float4*)(dst + tc * 4)      = v0;
            *(float4*)(dst + 64 + tc * 4) = v1;
        } else {
            float* dst = C + (size_t)(m0 + row) * EMBED + n0;
            *(float4*)(dst + tc * 4)      = v0;
            *(float4*)(dst + 64 + tc * 4) = v1;
        }
    }
}

__global__ __launch_bounds__(256, 2) void qkv_gemm_kernel(
    const float* __restrict__ x,
    const float* __restrict__ wq, const float* __restrict__ bq,
    const float* __restrict__ wk, const float* __restrict__ bk,
    const float* __restrict__ wv, const float* __restrict__ bv)
{
    const int z = blockIdx.z;
    const float* W  = (z == 0) ? wq : (z == 1) ? wk : wv;
    const float* Bi = (z == 0) ? bq : (z == 1) ? bk : bv;
    sgemm_body(x, W, Bi, g_QKV[z], 1);
}

__global__ __launch_bounds__(256, 2) void out_gemm_kernel(
    const float* __restrict__ wo, const float* __restrict__ bo,
    float* __restrict__ out)
{
    sgemm_body(g_A, wo, bo, out, 0);
}

// ---------------------------------------------------------------------------
// Flash attention, fp32. Block = 64 q-rows x one (b,h). 256 threads (16x16).
// Thread (ty,tx) owns S rows ty*4..+3 and S cols {tx, tx+16, tx+32, tx+48},
// and O cols tx*8..+7.
// K is stored in smem as XOR-swizzled float4 chunks (conflict-free loads).
// ---------------------------------------------------------------------------
#define QS_PITCH 132
// floats: Qs 64*132 + Ks 64*128 + Vs 64*128 + Ps 64*65
#define ATTN_SMEM_FLOATS (64 * QS_PITCH + 64 * 128 + 64 * 128 + 64 * 65)
#define ATTN_SMEM_BYTES  (ATTN_SMEM_FLOATS * 4)

__global__ __launch_bounds__(256) void attn_kernel()
{
    extern __shared__ float sm[];
    float*  Qs  = sm;                                  // [64][132]
    float4* Ks4 = (float4*)(sm + 64 * QS_PITCH);       // [64][32] swizzled
    float*  Vs  = sm + 64 * QS_PITCH + 64 * 128;       // [64][128]
    float*  Ps  = Vs + 64 * 128;                       // [64][65]

    const int tid = threadIdx.x;
    const int tx = tid & 15, ty = tid >> 4;
    const int bh = blockIdx.y;                         // b*16 + h
    const int q0 = blockIdx.x * 64;

    const float* Qb = g_QKV[0] + (size_t)bh * SEQ * HDIM;
    const float* Kb = g_QKV[1] + (size_t)bh * SEQ * HDIM;
    const float* Vb = g_QKV[2] + (size_t)bh * SEQ * HDIM;

    const float scale = kScale;

    // Load Q tile once, pre-scaled
#pragma unroll
    for (int i = 0; i < 8; i++) {
        int idx = tid + i * 256;
        int r = idx >> 5, c = (idx & 31) * 4;
        float4 v = *(const float4*)(Qb + (size_t)(q0 + r) * HDIM + c);
        float* d = Qs + r * QS_PITCH + c;
        d[0] = v.x * scale; d[1] = v.y * scale;
        d[2] = v.z * scale; d[3] = v.w * scale;
    }

    float m_r[4], l_r[4], O[4][8];
#pragma unroll
    for (int i = 0; i < 4; i++) {
        m_r[i] = -1e30f; l_r[i] = 0.0f;
#pragma unroll
        for (int c = 0; c < 8; c++) O[i][c] = 0.0f;
    }

    for (int kt = 0; kt < SEQ / 64; kt++) {
        __syncthreads();   // prev PV done (and Q store visible on iter 0)
        const int k0 = kt * 64;
#pragma unroll
        for (int i = 0; i < 8; i++) {
            int idx = tid + i * 256;
            int r = idx >> 5, c4 = idx & 31;
            float4 kv = *(const float4*)(Kb + (size_t)(k0 + r) * HDIM + c4 * 4);
            Ks4[r * 32 + (c4 ^ (r & 7))] = kv;         // swizzled store
            float4 vv = *(const float4*)(Vb + (size_t)(k0 + r) * HDIM + c4 * 4);
            *(float4*)(Vs + r * 128 + c4 * 4) = vv;
        }
        __syncthreads();

        // S = (Q*scale) @ K^T  (4x4 per thread)
        float s[4][4];
#pragma unroll
        for (int i = 0; i < 4; i++)
#pragma unroll
            for (int j = 0; j < 4; j++) s[i][j] = 0.0f;

#pragma unroll 4
        for (int kc = 0; kc < 32; kc++) {
            float4 q4[4], k4[4];
#pragma unroll
            for (int i = 0; i < 4; i++)
                q4[i] = *(const float4*)(Qs + (ty * 4 + i) * QS_PITCH + kc * 4);
#pragma unroll
            for (int j = 0; j < 4; j++) {
                int c = tx + 16 * j;
                k4[j] = Ks4[c * 32 + (kc ^ (c & 7))];  // swizzled load
            }
#pragma unroll
            for (int i = 0; i < 4; i++)
#pragma unroll
                for (int j = 0; j < 4; j++) {
                    s[i][j] = fmaf(q4[i].x, k4[j].x, s[i][j]);
                    s[i][j] = fmaf(q4[i].y, k4[j].y, s[i][j]);
                    s[i][j] = fmaf(q4[i].z, k4[j].z, s[i][j]);
                    s[i][j] = fmaf(q4[i].w, k4[j].w, s[i][j]);
                }
        }

        // Online softmax (row state replicated across the 16 tx lanes)
#pragma unroll
        for (int i = 0; i < 4; i++) {
            float mt = fmaxf(fmaxf(s[i][0], s[i][1]), fmaxf(s[i][2], s[i][3]));
#pragma unroll
            for (int o = 8; o > 0; o >>= 1)
                mt = fmaxf(mt, __shfl_xor_sync(0xffffffffu, mt, o));
            float mn = fmaxf(m_r[i], mt);
            float alpha = __expf(m_r[i] - mn);   // 0 on first tile (exp(-1e30))
            float ls = 0.0f;
#pragma unroll
            for (int j = 0; j < 4; j++) {
                float p = __expf(s[i][j] - mn);
                s[i][j] = p; ls += p;
            }
#pragma unroll
            for (int o = 8; o > 0; o >>= 1)
                ls += __shfl_xor_sync(0xffffffffu, ls, o);
            l_r[i] = l_r[i] * alpha + ls;
            m_r[i] = mn;
#pragma unroll
            for (int c = 0; c < 8; c++) O[i][c] *= alpha;
#pragma unroll
            for (int j = 0; j < 4; j++)
                Ps[(ty * 4 + i) * 65 + tx + 16 * j] = s[i][j];
        }
        __syncthreads();

        // O += P @ V
#pragma unroll 4
        for (int j = 0; j < 64; j++) {
            float4 v0 = *(const float4*)(Vs + j * 128 + tx * 8);
            float4 v1 = *(const float4*)(Vs + j * 128 + tx * 8 + 4);
#pragma unroll
            for (int i = 0; i < 4; i++) {
                float p = Ps[(ty * 4 + i) * 65 + j];
                O[i][0] = fmaf(p, v0.x, O[i][0]);
                O[i][1] = fmaf(p, v0.y, O[i][1]);
                O[i][2] = fmaf(p, v0.z, O[i][2]);
                O[i][3] = fmaf(p, v0.w, O[i][3]);
                O[i][4] = fmaf(p, v1.x, O[i][4]);
                O[i][5] = fmaf(p, v1.y, O[i][5]);
                O[i][6] = fmaf(p, v1.z, O[i][6]);
                O[i][7] = fmaf(p, v1.w, O[i][7]);
            }
        }
    }

    // Epilogue: normalize and write to [b, t, d] (d = h*128 + hd)
    const int b_ = bh >> 4, h_ = bh & 15;
#pragma unroll
    for (int i = 0; i < 4; i++) {
        float inv = 1.0f / l_r[i];
        int t = q0 + ty * 4 + i;
        float* dst = g_A + ((size_t)(b_ * SEQ + t)) * EMBED + h_ * HDIM + tx * 8;
        float4 o0 = make_float4(O[i][0] * inv, O[i][1] * inv,
                                O[i][2] * inv, O[i][3] * inv);
        float4 o1 = make_float4(O[i][4] * inv, O[i][5] * inv,
                                O[i][6] * inv, O[i][7] * inv);
        *(float4*)dst       = o0;
        *(float4*)(dst + 4) = o1;
    }
}

// ---------------------------------------------------------------------------
// Launch: QKV GEMMs (fused into one grid, z selects matrix) -> attention ->
// output projection. All on the default stream, graph-capturable, no allocs.
// ---------------------------------------------------------------------------
extern "C" void kernel_launch(void* const* d_in, const int* in_sizes, int n_in,
                              void* d_out, int out_size)
{
    (void)in_sizes; (void)n_in; (void)out_size;
    const float* x  = (const float*)d_in[0];
    const float* wq = (const float*)d_in[1];
    const float* bq = (const float*)d_in[2];
    const float* wk = (const float*)d_in[3];
    const float* bk = (const float*)d_in[4];
    const float* wv = (const float*)d_in[5];
    const float* bv = (const float*)d_in[6];
    const float* wo = (const float*)d_in[7];
    const float* bo = (const float*)d_in[8];
    float* out = (float*)d_out;

    // Opt-in to >48KB dynamic smem for the attention kernel (idempotent).
    cudaFuncSetAttribute(attn_kernel,
                         cudaFuncAttributeMaxDynamicSharedMemorySize,
                         ATTN_SMEM_BYTES);

    qkv_gemm_kernel<<<dim3(16, 32, 3), 256>>>(x, wq, bq, wk, bk, wv, bv);
    attn_kernel<<<dim3(32, 32), 256, ATTN_SMEM_BYTES>>>();
    out_gemm_kernel<<<dim3(16, 32), 256>>>(wo, bo, out);
}

// round 9
// speedup vs baseline: 1.0016x; 1.0005x over previous
#include <cuda_runtime.h>

// Problem constants
#define EMBED 2048
#define NHEAD 16
#define HDIM  128
#define BATCH 2
#define SEQ   2048
#define NTOK  (BATCH * SEQ)   // 4096

__device__ __constant__ float kScale = 0.022097086912079612f;  // 2048^-0.5

// Scratch (static __device__ globals: allocation-free per harness rules)
// Layout [3][b*16+h][t][hd]  (Q,K,V)
__device__ float g_QKV[3][(size_t)BATCH * NHEAD * SEQ * HDIM];
// Attention output in [b, t, d] layout (d = h*128 + hd), ready for the O-proj GEMM
__device__ float g_A[(size_t)NTOK * EMBED];

// ---------------------------------------------------------------------------
// SGEMM: C[4096 x 2048] = A[4096 x 2048] @ B[2048 x 2048] + bias
// 128x128 block tile, BK=8, 256 threads, 8x8 per thread.
// scatter=1: n-block == head; write to [b*16+h][t][hd] layout (for Q/K/V).
// scatter=0: plain row-major write.
// ---------------------------------------------------------------------------
__device__ __forceinline__ void sgemm_body(
    const float* __restrict__ A, const float* __restrict__ B,
    const float* __restrict__ bias, float* __restrict__ C, int scatter)
{
    __shared__ float As[8][132];   // transposed: As[k][m], padded
    __shared__ float Bs[8][128];   // Bs[k][n]

    const int tid = threadIdx.x;
    const int tr = tid >> 4;       // 0..15
    const int tc = tid & 15;       // 0..15
    const int m0 = blockIdx.y * 128;
    const int n0 = blockIdx.x * 128;

    float acc[8][8];
#pragma unroll
    for (int i = 0; i < 8; i++)
#pragma unroll
        for (int j = 0; j < 8; j++) acc[i][j] = 0.0f;

    const int a_row = tid >> 1;          // 0..127
    const int a_c   = (tid & 1) * 4;     // 0 or 4 within BK=8
    const int b_row = tid >> 5;          // 0..7
    const int b_c   = (tid & 31) * 4;    // 0..124

    const float* Ap = A + (size_t)(m0 + a_row) * EMBED + a_c;
    const float* Bp = B + (size_t)b_row * EMBED + n0 + b_c;

    for (int kt = 0; kt < EMBED / 8; kt++) {
        float4 av = *(const float4*)Ap;
        float4 bv = *(const float4*)Bp;
        __syncthreads();                 // previous tile's compute done
        As[a_c + 0][a_row] = av.x;
        As[a_c + 1][a_row] = av.y;
        As[a_c + 2][a_row] = av.z;
        As[a_c + 3][a_row] = av.w;
        *(float4*)&Bs[b_row][b_c] = bv;
        __syncthreads();

#pragma unroll
        for (int k = 0; k < 8; k++) {
            float4 a0 = *(const float4*)&As[k][tr * 4];
            float4 a1 = *(const float4*)&As[k][64 + tr * 4];
            float4 b0 = *(const float4*)&Bs[k][tc * 4];
            float4 b1 = *(const float4*)&Bs[k][64 + tc * 4];
            float ar[8] = {a0.x, a0.y, a0.z, a0.w, a1.x, a1.y, a1.z, a1.w};
            float br[8] = {b0.x, b0.y, b0.z, b0.w, b1.x, b1.y, b1.z, b1.w};
#pragma unroll
            for (int i = 0; i < 8; i++)
#pragma unroll
                for (int j = 0; j < 8; j++)
                    acc[i][j] = fmaf(ar[i], br[j], acc[i][j]);
        }
        Ap += 8;
        Bp += (size_t)8 * EMBED;
    }

    float4 bz0 = *(const float4*)(bias + n0 + tc * 4);
    float4 bz1 = *(const float4*)(bias + n0 + 64 + tc * 4);

#pragma unroll
    for (int i = 0; i < 8; i++) {
        const int row = (i < 4) ? (tr * 4 + i) : (64 + tr * 4 + (i - 4));
        float4 v0 = make_float4(acc[i][0] + bz0.x, acc[i][1] + bz0.y,
                                acc[i][2] + bz0.z, acc[i][3] + bz0.w);
        float4 v1 = make_float4(acc[i][4] + bz1.x, acc[i][5] + bz1.y,
                                acc[i][6] + bz1.z, acc[i][7] + bz1.w);
        if (scatter) {
            const int bb = m0 >> 11;              // batch index
            const int t  = (m0 & 2047) + row;     // position within sequence
            float* dst = C + ((size_t)(bb * NHEAD + blockIdx.x) * SEQ + t) * HDIM;
            *(float4*)(dst + tc * 4)      = v0;
            *(float4*)(dst + 64 + tc * 4) = v1;
        } else {
            float* dst = C + (size_t)(m0 + row) * EMBED + n0;
            *(float4*)(dst + tc * 4)      = v0;
            *(float4*)(dst + 64 + tc * 4) = v1;
        }
    }
}

__global__ __launch_bounds__(256, 2) void qkv_gemm_kernel(
    const float* __restrict__ x,
    const float* __restrict__ wq, const float* __restrict__ bq,
    const float* __restrict__ wk, const float* __restrict__ bk,
    const float* __restrict__ wv, const float* __restrict__ bv)
{
    const int z = blockIdx.z;
    const float* W  = (z == 0) ? wq : (z == 1) ? wk : wv;
    const float* Bi = (z == 0) ? bq : (z == 1) ? bk : bv;
    sgemm_body(x, W, Bi, g_QKV[z], 1);
}

__global__ __launch_bounds__(256, 2) void out_gemm_kernel(
    const float* __restrict__ wo, const float* __restrict__ bo,
    float* __restrict__ out)
{
    sgemm_body(g_A, wo, bo, out, 0);
}

// ---------------------------------------------------------------------------
// Flash attention, fp32. Block = 64 q-rows x one (b,h). 256 threads (16x16).
// Thread (ty,tx) owns S rows ty*4..+3 and S cols {tx, tx+16, tx+32, tx+48},
// and O cols tx*8..+7.
// K is stored in smem as XOR-swizzled float4 chunks (conflict-free loads).
// ---------------------------------------------------------------------------
#define QS_PITCH 132
// floats: Qs 64*132 + Ks 64*128 + Vs 64*128 + Ps 64*65
#define ATTN_SMEM_FLOATS (64 * QS_PITCH + 64 * 128 + 64 * 128 + 64 * 65)
#define ATTN_SMEM_BYTES  (ATTN_SMEM_FLOATS * 4)

__global__ __launch_bounds__(256) void attn_kernel()
{
    extern __shared__ float sm[];
    float*  Qs  = sm;                                  // [64][132]
    float4* Ks4 = (float4*)(sm + 64 * QS_PITCH);       // [64][32] swizzled
    float*  Vs  = sm + 64 * QS_PITCH + 64 * 128;       // [64][128]
    float*  Ps  = Vs + 64 * 128;                       // [64][65]

    const int tid = threadIdx.x;
    const int tx = tid & 15, ty = tid >> 4;
    const int bh = blockIdx.y;                         // b*16 + h
    const int q0 = blockIdx.x * 64;

    const float* Qb = g_QKV[0] + (size_t)bh * SEQ * HDIM;
    const float* Kb = g_QKV[1] + (size_t)bh * SEQ * HDIM;
    const float* Vb = g_QKV[2] + (size_t)bh * SEQ * HDIM;

    const float scale = kScale;

    // Load Q tile once, pre-scaled
#pragma unroll
    for (int i = 0; i < 8; i++) {
        int idx = tid + i * 256;
        int r = idx >> 5, c = (idx & 31) * 4;
        float4 v = *(const float4*)(Qb + (size_t)(q0 + r) * HDIM + c);
        float* d = Qs + r * QS_PITCH + c;
        d[0] = v.x * scale; d[1] = v.y * scale;
        d[2] = v.z * scale; d[3] = v.w * scale;
    }

    float m_r[4], l_r[4], O[4][8];
#pragma unroll
    for (int i = 0; i < 4; i++) {
        m_r[i] = -1e30f; l_r[i] = 0.0f;
#pragma unroll
        for (int c = 0; c < 8; c++) O[i][c] = 0.0f;
    }

    for (int kt = 0; kt < SEQ / 64; kt++) {
        __syncthreads();   // prev PV done (and Q store visible on iter 0)
        const int k0 = kt * 64;
#pragma unroll
        for (int i = 0; i < 8; i++) {
            int idx = tid + i * 256;
            int r = idx >> 5, c4 = idx & 31;
            float4 kv = *(const float4*)(Kb + (size_t)(k0 + r) * HDIM + c4 * 4);
            Ks4[r * 32 + (c4 ^ (r & 7))] = kv;         // swizzled store
            float4 vv = *(const float4*)(Vb + (size_t)(k0 + r) * HDIM + c4 * 4);
            *(float4*)(Vs + r * 128 + c4 * 4) = vv;
        }
        __syncthreads();

        // S = (Q*scale) @ K^T  (4x4 per thread)
        float s[4][4];
#pragma unroll
        for (int i = 0; i < 4; i++)
#pragma unroll
            for (int j = 0; j < 4; j++) s[i][j] = 0.0f;

#pragma unroll 4
        for (int kc = 0; kc < 32; kc++) {
            float4 q4[4], k4[4];
#pragma unroll
            for (int i = 0; i < 4; i++)
                q4[i] = *(const float4*)(Qs + (ty * 4 + i) * QS_PITCH + kc * 4);
#pragma unroll
            for (int j = 0; j < 4; j++) {
                int c = tx + 16 * j;
                k4[j] = Ks4[c * 32 + (kc ^ (c & 7))];  // swizzled load
            }
#pragma unroll
            for (int i = 0; i < 4; i++)
#pragma unroll
                for (int j = 0; j < 4; j++) {
                    s[i][j] = fmaf(q4[i].x, k4[j].x, s[i][j]);
                    s[i][j] = fmaf(q4[i].y, k4[j].y, s[i][j]);
                    s[i][j] = fmaf(q4[i].z, k4[j].z, s[i][j]);
                    s[i][j] = fmaf(q4[i].w, k4[j].w, s[i][j]);
                }
        }

        // Online softmax (row state replicated across the 16 tx lanes)
#pragma unroll
        for (int i = 0; i < 4; i++) {
            float mt = fmaxf(fmaxf(s[i][0], s[i][1]), fmaxf(s[i][2], s[i][3]));
#pragma unroll
            for (int o = 8; o > 0; o >>= 1)
                mt = fmaxf(mt, __shfl_xor_sync(0xffffffffu, mt, o));
            float mn = fmaxf(m_r[i], mt);
            float alpha = __expf(m_r[i] - mn);   // 0 on first tile (exp(-1e30))
            float ls = 0.0f;
#pragma unroll
            for (int j = 0; j < 4; j++) {
                float p = __expf(s[i][j] - mn);
                s[i][j] = p; ls += p;
            }
#pragma unroll
            for (int o = 8; o > 0; o >>= 1)
                ls += __shfl_xor_sync(0xffffffffu, ls, o);
            l_r[i] = l_r[i] * alpha + ls;
            m_r[i] = mn;
#pragma unroll
            for (int c = 0; c < 8; c++) O[i][c] *= alpha;
#pragma unroll
            for (int j = 0; j < 4; j++)
                Ps[(ty * 4 + i) * 65 + tx + 16 * j] = s[i][j];
        }
        __syncthreads();

        // O += P @ V
#pragma unroll 4
        for (int j = 0; j < 64; j++) {
            float4 v0 = *(const float4*)(Vs + j * 128 + tx * 8);
            float4 v1 = *(const float4*)(Vs + j * 128 + tx * 8 + 4);
#pragma unroll
            for (int i = 0; i < 4; i++) {
                float p = Ps[(ty * 4 + i) * 65 + j];
                O[i][0] = fmaf(p, v0.x, O[i][0]);
                O[i][1] = fmaf(p, v0.y, O[i][1]);
                O[i][2] = fmaf(p, v0.z, O[i][2]);
                O[i][3] = fmaf(p, v0.w, O[i][3]);
                O[i][4] = fmaf(p, v1.x, O[i][4]);
                O[i][5] = fmaf(p, v1.y, O[i][5]);
                O[i][6] = fmaf(p, v1.z, O[i][6]);
                O[i][7] = fmaf(p, v1.w, O[i][7]);
            }
        }
    }

    // Epilogue: normalize and write to [b, t, d] (d = h*128 + hd)
    const int b_ = bh >> 4, h_ = bh & 15;
#pragma unroll
    for (int i = 0; i < 4; i++) {
        float inv = 1.0f / l_r[i];
        int t = q0 + ty * 4 + i;
        float* dst = g_A + ((size_t)(b_ * SEQ + t)) * EMBED + h_ * HDIM + tx * 8;
        float4 o0 = make_float4(O[i][0] * inv, O[i][1] * inv,
                                O[i][2] * inv, O[i][3] * inv);
        float4 o1 = make_float4(O[i][4] * inv, O[i][5] * inv,
                                O[i][6] * inv, O[i][7] * inv);
        *(float4*)dst       = o0;
        *(float4*)(dst + 4) = o1;
    }
}

// ---------------------------------------------------------------------------
// Launch: QKV GEMMs (fused into one grid, z selects matrix) -> attention ->
// output projection. All on the default stream, graph-capturable, no allocs.
// ---------------------------------------------------------------------------
extern "C" void kernel_launch(void* const* d_in, const int* in_sizes, int n_in,
                              void* d_out, int out_size)
{
    (void)in_sizes; (void)n_in; (void)out_size;
    const float* x  = (const float*)d_in[0];
    const float* wq = (const float*)d_in[1];
    const float* bq = (const float*)d_in[2];
    const float* wk = (const float*)d_in[3];
    const float* bk = (const float*)d_in[4];
    const float* wv = (const float*)d_in[5];
    const float* bv = (const float*)d_in[6];
    const float* wo = (const float*)d_in[7];
    const float* bo = (const float*)d_in[8];
    float* out = (float*)d_out;

    // Opt-in to >48KB dynamic smem for the attention kernel (idempotent).
    cudaFuncSetAttribute(attn_kernel,
                         cudaFuncAttributeMaxDynamicSharedMemorySize,
                         ATTN_SMEM_BYTES);

    qkv_gemm_kernel<<<dim3(16, 32, 3), 256>>>(x, wq, bq, wk, bk, wv, bv);
    attn_kernel<<<dim3(32, 32), 256, ATTN_SMEM_BYTES>>>();
    out_gemm_kernel<<<dim3(16, 32), 256>>>(wo, bo, out);
}

// round 12
// speedup vs baseline: 1.3765x; 1.3743x over previous
#include <cuda_runtime.h>
#include <cuda_bf16.h>
#include <cstdint>

// Problem constants
#define EMBED 2048
#define NHEAD 16
#define HDIM  128
#define BATCH 2
#define SEQ   2048
#define NTOK  (BATCH * SEQ)   // 4096

__device__ __constant__ float kScale = 0.022097086912079612f;  // 2048^-0.5

// ---------------------------------------------------------------------------
// Static device scratch (allocation-free per harness rules)
// ---------------------------------------------------------------------------
__device__ float g_QKV[3][(size_t)BATCH * NHEAD * SEQ * HDIM];   // fp32 [qkv][bh][t][hd]
__device__ float g_A[(size_t)NTOK * EMBED];                      // attention out, [b,t,d]

__device__ __nv_bfloat16 g_Xh[(size_t)NTOK * EMBED];             // x hi/lo
__device__ __nv_bfloat16 g_Xl[(size_t)NTOK * EMBED];
__device__ __nv_bfloat16 g_Ah[(size_t)NTOK * EMBED];             // attn-out hi/lo
__device__ __nv_bfloat16 g_Al[(size_t)NTOK * EMBED];
__device__ __nv_bfloat16 g_Wh[4][(size_t)EMBED * EMBED];         // W^T hi/lo: [n][k]
__device__ __nv_bfloat16 g_Wl[4][(size_t)EMBED * EMBED];

// ---------------------------------------------------------------------------
// sm_80-era PTX helpers (base-target ISA; no 'a' features)
// ---------------------------------------------------------------------------
__device__ __forceinline__ uint32_t smem_u32(const void* p) {
    uint32_t a;
    asm("{ .reg .u64 t; cvta.to.shared.u64 t, %1; cvt.u32.u64 %0, t; }"
        : "=r"(a) : "l"(p));
    return a;
}

__device__ __forceinline__ void ldsm4(uint32_t* r, uint32_t addr) {
    asm volatile("ldmatrix.sync.aligned.m8n8.x4.shared.b16 {%0,%1,%2,%3}, [%4];"
                 : "=r"(r[0]), "=r"(r[1]), "=r"(r[2]), "=r"(r[3]) : "r"(addr));
}

__device__ __forceinline__ void mma_bf16(float* c, const uint32_t* a,
                                         const uint32_t* b) {
    asm volatile(
        "mma.sync.aligned.m16n8k16.row.col.f32.bf16.bf16.f32 "
        "{%0,%1,%2,%3}, {%4,%5,%6,%7}, {%8,%9}, {%0,%1,%2,%3};"
        : "+f"(c[0]), "+f"(c[1]), "+f"(c[2]), "+f"(c[3])
        : "r"(a[0]), "r"(a[1]), "r"(a[2]), "r"(a[3]), "r"(b[0]), "r"(b[1]));
}

// ---------------------------------------------------------------------------
// Prep kernels: fp32 -> bf16 hi/lo split (+ transpose for weights)
// ---------------------------------------------------------------------------
__device__ __forceinline__ void bf16_split(float v, __nv_bfloat16& h, __nv_bfloat16& l) {
    h = __float2bfloat16_rn(v);
    l = __float2bfloat16_rn(v - __bfloat162float(h));
}

// which=0: src=x -> g_Xh/g_Xl;  which=1: g_A -> g_Ah/g_Al
__global__ void split_kernel(const float* __restrict__ src, int which) {
    size_t i = (size_t)blockIdx.x * blockDim.x + threadIdx.x;  // float4 index
    const float* s = which ? g_A : src;
    __nv_bfloat16* dh = which ? g_Ah : g_Xh;
    __nv_bfloat16* dl = which ? g_Al : g_Xl;
    float4 v = ((const float4*)s)[i];
    __nv_bfloat16 h0, l0, h1, l1, h2, l2, h3, l3;
    bf16_split(v.x, h0, l0); bf16_split(v.y, h1, l1);
    bf16_split(v.z, h2, l2); bf16_split(v.w, h3, l3);
    ((__nv_bfloat162*)dh)[i * 2 + 0] = __halves2bfloat162(h0, h1);
    ((__nv_bfloat162*)dh)[i * 2 + 1] = __halves2bfloat162(h2, h3);
    ((__nv_bfloat162*)dl)[i * 2 + 0] = __halves2bfloat162(l0, l1);
    ((__nv_bfloat162*)dl)[i * 2 + 1] = __halves2bfloat162(l2, l3);
}

// Transpose + split: w[k][n] fp32 -> g_Wh/g_Wl[z][n][k] bf16
__global__ void wsplit_kernel(const float* __restrict__ wq,
                              const float* __restrict__ wk,
                              const float* __restrict__ wv,
                              const float* __restrict__ wo) {
    __shared__ float tile[32][33];
    const int z = blockIdx.z;
    const float* w = (z == 0) ? wq : (z == 1) ? wk : (z == 2) ? wv : wo;
    const int n0 = blockIdx.x * 32, k0 = blockIdx.y * 32;
    const int tx = threadIdx.x, ty = threadIdx.y;  // 32 x 8
#pragma unroll
    for (int i = 0; i < 4; i++)
        tile[ty + 8 * i][tx] = w[(size_t)(k0 + ty + 8 * i) * EMBED + n0 + tx];
    __syncthreads();
#pragma unroll
    for (int i = 0; i < 4; i++) {
        float v = tile[tx][ty + 8 * i];
        __nv_bfloat16 h, l;
        bf16_split(v, h, l);
        size_t off = (size_t)(n0 + ty + 8 * i) * EMBED + k0 + tx;
        g_Wh[z][off] = h;
        g_Wl[z][off] = l;
    }
}

// ---------------------------------------------------------------------------
// mma.sync GEMM: C[4096 x 2048] = A @ W^T + bias  via bf16 hi/lo split
// (hi*hi + hi*lo + lo*hi), fp32 accum in registers.
// CTA tile 128x128, 256 threads (8 warps, 64x32 warp tiles), k-chunk 32,
// double-buffered smem, 80-byte row pitch (conflict-free ldmatrix).
// ---------------------------------------------------------------------------
#define PITCH_B   80                     // bytes per smem row (40 bf16)
#define ASZ       (128 * PITCH_B)        // 10240 bytes per array
#define STAGE_B   (4 * ASZ)              // Ah, Al, Bh, Bl
#define GEMM_SMEM (2 * STAGE_B)          // 81920 bytes
#define NCHUNK    (EMBED / 32)           // 64

__device__ __forceinline__ void mma_gemm_body(
    const __nv_bfloat16* __restrict__ Ah, const __nv_bfloat16* __restrict__ Al,
    const __nv_bfloat16* __restrict__ Bh, const __nv_bfloat16* __restrict__ Bl,
    const float* __restrict__ bias, float* __restrict__ outp,
    int scatter, int head)
{
    extern __shared__ char smem[];
    const uint32_t sbase = smem_u32(smem);

    const int tid  = threadIdx.x;
    const int wid  = tid >> 5, lane = tid & 31;
    const int m0   = blockIdx.y * 128;
    const int n0   = blockIdx.x * 128;

    // Loader mapping: 256 threads -> 128 rows x 2 halves of a 64B chunk-row
    const int lrow = tid >> 1;
    const int lhalf = tid & 1;
    const __nv_bfloat16* pAh = Ah + (size_t)(m0 + lrow) * EMBED + lhalf * 16;
    const __nv_bfloat16* pAl = Al + (size_t)(m0 + lrow) * EMBED + lhalf * 16;
    const __nv_bfloat16* pBh = Bh + (size_t)(n0 + lrow) * EMBED + lhalf * 16;
    const __nv_bfloat16* pBl = Bl + (size_t)(n0 + lrow) * EMBED + lhalf * 16;

    float acc[4][4][4];
#pragma unroll
    for (int i = 0; i < 4; i++)
#pragma unroll
        for (int j = 0; j < 4; j++)
#pragma unroll
            for (int r = 0; r < 4; r++) acc[i][j][r] = 0.0f;

    float4 pf[8];
    auto gload = [&](int c) {
        const size_t ko = (size_t)c * 32;
        pf[0] = *(const float4*)(pAh + ko); pf[1] = *(const float4*)(pAh + ko + 8);
        pf[2] = *(const float4*)(pAl + ko); pf[3] = *(const float4*)(pAl + ko + 8);
        pf[4] = *(const float4*)(pBh + ko); pf[5] = *(const float4*)(pBh + ko + 8);
        pf[6] = *(const float4*)(pBl + ko); pf[7] = *(const float4*)(pBl + ko + 8);
    };
    auto sstore = [&](int stage) {
        char* sb = smem + stage * STAGE_B;
        const uint32_t o = (uint32_t)lrow * PITCH_B + lhalf * 32;
        *(float4*)(sb + o)            = pf[0]; *(float4*)(sb + o + 16)           = pf[1];
        *(float4*)(sb + ASZ + o)      = pf[2]; *(float4*)(sb + ASZ + o + 16)     = pf[3];
        *(float4*)(sb + 2*ASZ + o)    = pf[4]; *(float4*)(sb + 2*ASZ + o + 16)   = pf[5];
        *(float4*)(sb + 3*ASZ + o)    = pf[6]; *(float4*)(sb + 3*ASZ + o + 16)   = pf[7];
    };

    const int wm = (wid & 1) * 64;        // warp m-offset within CTA tile
    const int wn = (wid >> 1) * 32;       // warp n-offset
    const uint32_t arow = lane & 15;      // ldmatrix A row select
    const uint32_t akh  = lane >> 4;      // A k-half (16B)
    const uint32_t bn   = (lane & 7) + ((lane >> 4) & 1) * 8;  // B n select
    const uint32_t bkh  = (lane >> 3) & 1;                     // B k-half

    auto compute = [&](int stage) {
        const uint32_t s = sbase + stage * STAGE_B;
#pragma unroll
        for (int ks = 0; ks < 2; ks++) {
            uint32_t ah[4][4], al[4][4];
#pragma unroll
            for (int mi = 0; mi < 4; mi++) {
                const uint32_t ad = s + (wm + mi * 16 + arow) * PITCH_B
                                      + ks * 32 + akh * 16;
                ldsm4(ah[mi], ad);
                ldsm4(al[mi], ad + ASZ);
            }
            uint32_t bh[2][4], bl[2][4];
#pragma unroll
            for (int jj = 0; jj < 2; jj++) {
                const uint32_t bd = s + 2 * ASZ + (wn + jj * 16 + bn) * PITCH_B
                                      + ks * 32 + bkh * 16;
                ldsm4(bh[jj], bd);
                ldsm4(bl[jj], bd + ASZ);
            }
#pragma unroll
            for (int mi = 0; mi < 4; mi++)
#pragma unroll
                for (int nj = 0; nj < 4; nj++) {
                    const uint32_t* bhp = &bh[nj >> 1][(nj & 1) * 2];
                    const uint32_t* blp = &bl[nj >> 1][(nj & 1) * 2];
                    mma_bf16(acc[mi][nj], ah[mi], bhp);   // hi*hi
                    mma_bf16(acc[mi][nj], ah[mi], blp);   // hi*lo
                    mma_bf16(acc[mi][nj], al[mi], bhp);   // lo*hi
                }
        }
    };

    // Software pipeline: prefetch global -> regs while computing current stage
    gload(0);
    sstore(0);
    __syncthreads();
    for (int c = 0; c < NCHUNK; c++) {
        if (c + 1 < NCHUNK) gload(c + 1);
        compute(c & 1);
        if (c + 1 < NCHUNK) {
            __syncthreads();
            sstore((c + 1) & 1);
            __syncthreads();
        }
    }

    // Epilogue: fragment layout -> global (+bias), optional head-scatter
    const int r0 = lane >> 2, c0 = (lane & 3) * 2;
#pragma unroll
    for (int mi = 0; mi < 4; mi++) {
#pragma unroll
        for (int ro = 0; ro < 2; ro++) {
            const int m = m0 + wm + mi * 16 + r0 + ro * 8;
            float* dst;
            if (scatter) {
                const int b = m >> 11, t = m & 2047;
                dst = outp + ((size_t)(b * NHEAD + head) * SEQ + t) * HDIM;
            } else {
                dst = outp + (size_t)m * EMBED + n0;
            }
#pragma unroll
            for (int nj = 0; nj < 4; nj++) {
                const int nl = wn + nj * 8 + c0;
                float2 v;
                v.x = acc[mi][nj][ro * 2 + 0] + __ldg(&bias[n0 + nl]);
                v.y = acc[mi][nj][ro * 2 + 1] + __ldg(&bias[n0 + nl + 1]);
                *(float2*)(dst + nl) = v;
            }
        }
    }
}

__global__ __launch_bounds__(256, 1) void qkv_mma_kernel(
    const float* bq, const float* bk, const float* bv)
{
    const int z = blockIdx.z;
    const float* bias = (z == 0) ? bq : (z == 1) ? bk : bv;
    mma_gemm_body(g_Xh, g_Xl, g_Wh[z], g_Wl[z], bias, g_QKV[z], 1, blockIdx.x);
}

__global__ __launch_bounds__(256, 1) void o_mma_kernel(
    const float* bo, float* out)
{
    mma_gemm_body(g_Ah, g_Al, g_Wh[3], g_Wl[3], bo, out, 0, 0);
}

// ---------------------------------------------------------------------------
// Flash attention, fp32 (unchanged, validated in R6; next round's target).
// ---------------------------------------------------------------------------
#define QS_PITCH 132
#define ATTN_SMEM_FLOATS (64 * QS_PITCH + 64 * 128 + 64 * 128 + 64 * 65)
#define ATTN_SMEM_BYTES  (ATTN_SMEM_FLOATS * 4)

__global__ __launch_bounds__(256) void attn_kernel()
{
    extern __shared__ float sm[];
    float*  Qs  = sm;                                  // [64][132]
    float4* Ks4 = (float4*)(sm + 64 * QS_PITCH);       // [64][32] swizzled
    float*  Vs  = sm + 64 * QS_PITCH + 64 * 128;       // [64][128]
    float*  Ps  = Vs + 64 * 128;                       // [64][65]

    const int tid = threadIdx.x;
    const int tx = tid & 15, ty = tid >> 4;
    const int bh = blockIdx.y;
    const int q0 = blockIdx.x * 64;

    const float* Qb = g_QKV[0] + (size_t)bh * SEQ * HDIM;
    const float* Kb = g_QKV[1] + (size_t)bh * SEQ * HDIM;
    const float* Vb = g_QKV[2] + (size_t)bh * SEQ * HDIM;

    const float scale = kScale;

#pragma unroll
    for (int i = 0; i < 8; i++) {
        int idx = tid + i * 256;
        int r = idx >> 5, c = (idx & 31) * 4;
        float4 v = *(const float4*)(Qb + (size_t)(q0 + r) * HDIM + c);
        float* d = Qs + r * QS_PITCH + c;
        d[0] = v.x * scale; d[1] = v.y * scale;
        d[2] = v.z * scale; d[3] = v.w * scale;
    }

    float m_r[4], l_r[4], O[4][8];
#pragma unroll
    for (int i = 0; i < 4; i++) {
        m_r[i] = -1e30f; l_r[i] = 0.0f;
#pragma unroll
        for (int c = 0; c < 8; c++) O[i][c] = 0.0f;
    }

    for (int kt = 0; kt < SEQ / 64; kt++) {
        __syncthreads();
        const int k0 = kt * 64;
#pragma unroll
        for (int i = 0; i < 8; i++) {
            int idx = tid + i * 256;
            int r = idx >> 5, c4 = idx & 31;
            float4 kv = *(const float4*)(Kb + (size_t)(k0 + r) * HDIM + c4 * 4);
            Ks4[r * 32 + (c4 ^ (r & 7))] = kv;
            float4 vv = *(const float4*)(Vb + (size_t)(k0 + r) * HDIM + c4 * 4);
            *(float4*)(Vs + r * 128 + c4 * 4) = vv;
        }
        __syncthreads();

        float s[4][4];
#pragma unroll
        for (int i = 0; i < 4; i++)
#pragma unroll
            for (int j = 0; j < 4; j++) s[i][j] = 0.0f;

#pragma unroll 4
        for (int kc = 0; kc < 32; kc++) {
            float4 q4[4], k4[4];
#pragma unroll
            for (int i = 0; i < 4; i++)
                q4[i] = *(const float4*)(Qs + (ty * 4 + i) * QS_PITCH + kc * 4);
#pragma unroll
            for (int j = 0; j < 4; j++) {
                int c = tx + 16 * j;
                k4[j] = Ks4[c * 32 + (kc ^ (c & 7))];
            }
#pragma unroll
            for (int i = 0; i < 4; i++)
#pragma unroll
                for (int j = 0; j < 4; j++) {
                    s[i][j] = fmaf(q4[i].x, k4[j].x, s[i][j]);
                    s[i][j] = fmaf(q4[i].y, k4[j].y, s[i][j]);
                    s[i][j] = fmaf(q4[i].z, k4[j].z, s[i][j]);
                    s[i][j] = fmaf(q4[i].w, k4[j].w, s[i][j]);
                }
        }

#pragma unroll
        for (int i = 0; i < 4; i++) {
            float mt = fmaxf(fmaxf(s[i][0], s[i][1]), fmaxf(s[i][2], s[i][3]));
#pragma unroll
            for (int o = 8; o > 0; o >>= 1)
                mt = fmaxf(mt, __shfl_xor_sync(0xffffffffu, mt, o));
            float mn = fmaxf(m_r[i], mt);
            float alpha = __expf(m_r[i] - mn);
            float ls = 0.0f;
#pragma unroll
            for (int j = 0; j < 4; j++) {
                float p = __expf(s[i][j] - mn);
                s[i][j] = p; ls += p;
            }
#pragma unroll
            for (int o = 8; o > 0; o >>= 1)
                ls += __shfl_xor_sync(0xffffffffu, ls, o);
            l_r[i] = l_r[i] * alpha + ls;
            m_r[i] = mn;
#pragma unroll
            for (int c = 0; c < 8; c++) O[i][c] *= alpha;
#pragma unroll
            for (int j = 0; j < 4; j++)
                Ps[(ty * 4 + i) * 65 + tx + 16 * j] = s[i][j];
        }
        __syncthreads();

#pragma unroll 4
        for (int j = 0; j < 64; j++) {
            float4 v0 = *(const float4*)(Vs + j * 128 + tx * 8);
            float4 v1 = *(const float4*)(Vs + j * 128 + tx * 8 + 4);
#pragma unroll
            for (int i = 0; i < 4; i++) {
                float p = Ps[(ty * 4 + i) * 65 + j];
                O[i][0] = fmaf(p, v0.x, O[i][0]);
                O[i][1] = fmaf(p, v0.y, O[i][1]);
                O[i][2] = fmaf(p, v0.z, O[i][2]);
                O[i][3] = fmaf(p, v0.w, O[i][3]);
                O[i][4] = fmaf(p, v1.x, O[i][4]);
                O[i][5] = fmaf(p, v1.y, O[i][5]);
                O[i][6] = fmaf(p, v1.z, O[i][6]);
                O[i][7] = fmaf(p, v1.w, O[i][7]);
            }
        }
    }

    const int b_ = bh >> 4, h_ = bh & 15;
#pragma unroll
    for (int i = 0; i < 4; i++) {
        float inv = 1.0f / l_r[i];
        int t = q0 + ty * 4 + i;
        float* dst = g_A + ((size_t)(b_ * SEQ + t)) * EMBED + h_ * HDIM + tx * 8;
        float4 o0 = make_float4(O[i][0] * inv, O[i][1] * inv,
                                O[i][2] * inv, O[i][3] * inv);
        float4 o1 = make_float4(O[i][4] * inv, O[i][5] * inv,
                                O[i][6] * inv, O[i][7] * inv);
        *(float4*)dst       = o0;
        *(float4*)(dst + 4) = o1;
    }
}

// ---------------------------------------------------------------------------
// Launch sequence
// ---------------------------------------------------------------------------
extern "C" void kernel_launch(void* const* d_in, const int* in_sizes, int n_in,
                              void* d_out, int out_size)
{
    (void)in_sizes; (void)n_in; (void)out_size;
    const float* x  = (const float*)d_in[0];
    const float* wq = (const float*)d_in[1];
    const float* bq = (const float*)d_in[2];
    const float* wk = (const float*)d_in[3];
    const float* bk = (const float*)d_in[4];
    const float* wv = (const float*)d_in[5];
    const float* bv = (const float*)d_in[6];
    const float* wo = (const float*)d_in[7];
    const float* bo = (const float*)d_in[8];
    float* out = (float*)d_out;

    cudaFuncSetAttribute(attn_kernel,
                         cudaFuncAttributeMaxDynamicSharedMemorySize,
                         ATTN_SMEM_BYTES);
    cudaFuncSetAttribute(qkv_mma_kernel,
                         cudaFuncAttributeMaxDynamicSharedMemorySize,
                         GEMM_SMEM);
    cudaFuncSetAttribute(o_mma_kernel,
                         cudaFuncAttributeMaxDynamicSharedMemorySize,
                         GEMM_SMEM);

    // 1. split x -> bf16 hi/lo
    split_kernel<<<(NTOK * EMBED / 4) / 256, 256>>>(x, 0);
    // 2. transpose + split all four weight matrices
    wsplit_kernel<<<dim3(EMBED / 32, EMBED / 32, 4), dim3(32, 8)>>>(wq, wk, wv, wo);
    // 3. QKV projections via bf16-split mma.sync
    qkv_mma_kernel<<<dim3(16, 32, 3), 256, GEMM_SMEM>>>(bq, bk, bv);
    // 4. attention (fp32)
    attn_kernel<<<dim3(32, 32), 256, ATTN_SMEM_BYTES>>>();
    // 5. split attention output -> bf16 hi/lo
    split_kernel<<<(NTOK * EMBED / 4) / 256, 256>>>(nullptr, 1);
    // 6. output projection via bf16-split mma.sync
    o_mma_kernel<<<dim3(16, 32, 1), 256, GEMM_SMEM>>>(bo, out);
}

// round 13
// speedup vs baseline: 2.4735x; 1.7969x over previous
#include <cuda_runtime.h>
#include <cuda_bf16.h>
#include <cstdint>

// Problem constants
#define EMBED 2048
#define NHEAD 16
#define HDIM  128
#define BATCH 2
#define SEQ   2048
#define NTOK  (BATCH * SEQ)   // 4096

__device__ __constant__ float kScale = 0.022097086912079612f;  // 2048^-0.5

// ---------------------------------------------------------------------------
// Static device scratch (allocation-free per harness rules)
// ---------------------------------------------------------------------------
__device__ __nv_bfloat16 g_Xh[(size_t)NTOK * EMBED];             // x hi/lo
__device__ __nv_bfloat16 g_Xl[(size_t)NTOK * EMBED];
__device__ __nv_bfloat16 g_Ah[(size_t)NTOK * EMBED];             // attn-out hi/lo
__device__ __nv_bfloat16 g_Al[(size_t)NTOK * EMBED];
__device__ __nv_bfloat16 g_Wh[4][(size_t)EMBED * EMBED];         // W^T hi/lo: [n][k]
__device__ __nv_bfloat16 g_Wl[4][(size_t)EMBED * EMBED];
// QKV in bf16 hi/lo, [bh][t][hd]; Q pre-scaled by kScale
__device__ __nv_bfloat16 g_Qh[(size_t)BATCH * NHEAD * SEQ * HDIM];
__device__ __nv_bfloat16 g_Ql[(size_t)BATCH * NHEAD * SEQ * HDIM];
__device__ __nv_bfloat16 g_Kh[(size_t)BATCH * NHEAD * SEQ * HDIM];
__device__ __nv_bfloat16 g_Kl[(size_t)BATCH * NHEAD * SEQ * HDIM];
__device__ __nv_bfloat16 g_Vh[(size_t)BATCH * NHEAD * SEQ * HDIM];
__device__ __nv_bfloat16 g_Vl[(size_t)BATCH * NHEAD * SEQ * HDIM];

// ---------------------------------------------------------------------------
// sm_80-era PTX helpers (base-target ISA; no 'a' features — R11 constraint)
// ---------------------------------------------------------------------------
__device__ __forceinline__ uint32_t smem_u32(const void* p) {
    uint32_t a;
    asm("{ .reg .u64 t; cvta.to.shared.u64 t, %1; cvt.u32.u64 %0, t; }"
        : "=r"(a) : "l"(p));
    return a;
}

__device__ __forceinline__ void ldsm4(uint32_t* r, uint32_t addr) {
    asm volatile("ldmatrix.sync.aligned.m8n8.x4.shared.b16 {%0,%1,%2,%3}, [%4];"
                 : "=r"(r[0]), "=r"(r[1]), "=r"(r[2]), "=r"(r[3]) : "r"(addr));
}
__device__ __forceinline__ void ldsm4t(uint32_t* r, uint32_t addr) {
    asm volatile("ldmatrix.sync.aligned.m8n8.x4.trans.shared.b16 {%0,%1,%2,%3}, [%4];"
                 : "=r"(r[0]), "=r"(r[1]), "=r"(r[2]), "=r"(r[3]) : "r"(addr));
}

__device__ __forceinline__ void mma_bf16(float* c, const uint32_t* a,
                                         const uint32_t* b) {
    asm volatile(
        "mma.sync.aligned.m16n8k16.row.col.f32.bf16.bf16.f32 "
        "{%0,%1,%2,%3}, {%4,%5,%6,%7}, {%8,%9}, {%0,%1,%2,%3};"
        : "+f"(c[0]), "+f"(c[1]), "+f"(c[2]), "+f"(c[3])
        : "r"(a[0]), "r"(a[1]), "r"(a[2]), "r"(a[3]), "r"(b[0]), "r"(b[1]));
}

__device__ __forceinline__ void cp16(uint32_t sdst, const void* gsrc) {
    asm volatile("cp.async.cg.shared.global [%0], [%1], 16;"
                 :: "r"(sdst), "l"(gsrc) : "memory");
}
#define CP_COMMIT asm volatile("cp.async.commit_group;" ::: "memory")
#define CP_WAIT0  asm volatile("cp.async.wait_group 0;" ::: "memory")
#define CP_WAIT1  asm volatile("cp.async.wait_group 1;" ::: "memory")

// Swizzle for 256B-pitch bf16 tiles: 16B chunk c of row r -> c XOR (r&7) in low 3 bits
__device__ __forceinline__ uint32_t swz(uint32_t row, uint32_t byte) {
    uint32_t c = byte >> 4;
    return row * 256 + ((((c ^ row) & 7u) | (c & 8u)) << 4) + (byte & 15u);
}

__device__ __forceinline__ void bf16_split(float v, __nv_bfloat16& h, __nv_bfloat16& l) {
    h = __float2bfloat16_rn(v);
    l = __float2bfloat16_rn(v - __bfloat162float(h));
}
// split (a,b) -> packed hi bf16x2, lo bf16x2 (low half = first element)
__device__ __forceinline__ void split_pack2(float a, float b, uint32_t& h, uint32_t& l) {
    __nv_bfloat16 ha, la, hb, lb;
    bf16_split(a, ha, la); bf16_split(b, hb, lb);
    __nv_bfloat162 H = __halves2bfloat162(ha, hb);
    __nv_bfloat162 L = __halves2bfloat162(la, lb);
    h = *reinterpret_cast<uint32_t*>(&H);
    l = *reinterpret_cast<uint32_t*>(&L);
}

// ---------------------------------------------------------------------------
// Prep kernels
// ---------------------------------------------------------------------------
__global__ void split_kernel(const float* __restrict__ src) {
    size_t i = (size_t)blockIdx.x * blockDim.x + threadIdx.x;  // float4 index
    float4 v = ((const float4*)src)[i];
    uint32_t h0, l0, h1, l1;
    split_pack2(v.x, v.y, h0, l0);
    split_pack2(v.z, v.w, h1, l1);
    ((uint32_t*)g_Xh)[i * 2 + 0] = h0; ((uint32_t*)g_Xh)[i * 2 + 1] = h1;
    ((uint32_t*)g_Xl)[i * 2 + 0] = l0; ((uint32_t*)g_Xl)[i * 2 + 1] = l1;
}

// Transpose + split: w[k][n] fp32 -> g_Wh/g_Wl[z][n][k] bf16
__global__ void wsplit_kernel(const float* __restrict__ wq,
                              const float* __restrict__ wk,
                              const float* __restrict__ wv,
                              const float* __restrict__ wo) {
    __shared__ float tile[32][33];
    const int z = blockIdx.z;
    const float* w = (z == 0) ? wq : (z == 1) ? wk : (z == 2) ? wv : wo;
    const int n0 = blockIdx.x * 32, k0 = blockIdx.y * 32;
    const int tx = threadIdx.x, ty = threadIdx.y;  // 32 x 8
#pragma unroll
    for (int i = 0; i < 4; i++)
        tile[ty + 8 * i][tx] = w[(size_t)(k0 + ty + 8 * i) * EMBED + n0 + tx];
    __syncthreads();
#pragma unroll
    for (int i = 0; i < 4; i++) {
        float v = tile[tx][ty + 8 * i];
        __nv_bfloat16 h, l;
        bf16_split(v, h, l);
        size_t off = (size_t)(n0 + ty + 8 * i) * EMBED + k0 + tx;
        g_Wh[z][off] = h;
        g_Wl[z][off] = l;
    }
}

// ---------------------------------------------------------------------------
// mma.sync GEMM (validated R12): C = A @ W^T + bias, bf16 hi/lo 3-pass.
// mode 0: fp32 row-major out.  mode 1: (acc+bias)*scale, split hi/lo,
//         scatter to [bh][t][hd] bf16 arrays (one head per blockIdx.x).
// ---------------------------------------------------------------------------
#define PITCH_B   80
#define ASZ       (128 * PITCH_B)
#define STAGE_B   (4 * ASZ)
#define GEMM_SMEM (2 * STAGE_B)
#define NCHUNK    (EMBED / 32)

__device__ __forceinline__ void mma_gemm_body(
    const __nv_bfloat16* __restrict__ Ah, const __nv_bfloat16* __restrict__ Al,
    const __nv_bfloat16* __restrict__ Bh, const __nv_bfloat16* __restrict__ Bl,
    const float* __restrict__ bias, float* __restrict__ outp,
    int mode, int head, __nv_bfloat16* outh, __nv_bfloat16* outl, float scale)
{
    extern __shared__ char smem[];
    const uint32_t sbase = smem_u32(smem);

    const int tid  = threadIdx.x;
    const int wid  = tid >> 5, lane = tid & 31;
    const int m0   = blockIdx.y * 128;
    const int n0   = blockIdx.x * 128;

    const int lrow = tid >> 1;
    const int lhalf = tid & 1;
    const __nv_bfloat16* pAh = Ah + (size_t)(m0 + lrow) * EMBED + lhalf * 16;
    const __nv_bfloat16* pAl = Al + (size_t)(m0 + lrow) * EMBED + lhalf * 16;
    const __nv_bfloat16* pBh = Bh + (size_t)(n0 + lrow) * EMBED + lhalf * 16;
    const __nv_bfloat16* pBl = Bl + (size_t)(n0 + lrow) * EMBED + lhalf * 16;

    float acc[4][4][4];
#pragma unroll
    for (int i = 0; i < 4; i++)
#pragma unroll
        for (int j = 0; j < 4; j++)
#pragma unroll
            for (int r = 0; r < 4; r++) acc[i][j][r] = 0.0f;

    float4 pf[8];
    auto gload = [&](int c) {
        const size_t ko = (size_t)c * 32;
        pf[0] = *(const float4*)(pAh + ko); pf[1] = *(const float4*)(pAh + ko + 8);
        pf[2] = *(const float4*)(pAl + ko); pf[3] = *(const float4*)(pAl + ko + 8);
        pf[4] = *(const float4*)(pBh + ko); pf[5] = *(const float4*)(pBh + ko + 8);
        pf[6] = *(const float4*)(pBl + ko); pf[7] = *(const float4*)(pBl + ko + 8);
    };
    auto sstore = [&](int stage) {
        char* sb = smem + stage * STAGE_B;
        const uint32_t o = (uint32_t)lrow * PITCH_B + lhalf * 32;
        *(float4*)(sb + o)            = pf[0]; *(float4*)(sb + o + 16)           = pf[1];
        *(float4*)(sb + ASZ + o)      = pf[2]; *(float4*)(sb + ASZ + o + 16)     = pf[3];
        *(float4*)(sb + 2*ASZ + o)    = pf[4]; *(float4*)(sb + 2*ASZ + o + 16)   = pf[5];
        *(float4*)(sb + 3*ASZ + o)    = pf[6]; *(float4*)(sb + 3*ASZ + o + 16)   = pf[7];
    };

    const int wm = (wid & 1) * 64;
    const int wn = (wid >> 1) * 32;
    const uint32_t arow = lane & 15;
    const uint32_t akh  = lane >> 4;
    const uint32_t bn   = (lane & 7) + ((lane >> 4) & 1) * 8;
    const uint32_t bkh  = (lane >> 3) & 1;

    auto compute = [&](int stage) {
        const uint32_t s = sbase + stage * STAGE_B;
#pragma unroll
        for (int ks = 0; ks < 2; ks++) {
            uint32_t ah[4][4], al[4][4];
#pragma unroll
            for (int mi = 0; mi < 4; mi++) {
                const uint32_t ad = s + (wm + mi * 16 + arow) * PITCH_B
                                      + ks * 32 + akh * 16;
                ldsm4(ah[mi], ad);
                ldsm4(al[mi], ad + ASZ);
            }
            uint32_t bh[2][4], bl[2][4];
#pragma unroll
            for (int jj = 0; jj < 2; jj++) {
                const uint32_t bd = s + 2 * ASZ + (wn + jj * 16 + bn) * PITCH_B
                                      + ks * 32 + bkh * 16;
                ldsm4(bh[jj], bd);
                ldsm4(bl[jj], bd + ASZ);
            }
#pragma unroll
            for (int mi = 0; mi < 4; mi++)
#pragma unroll
                for (int nj = 0; nj < 4; nj++) {
                    const uint32_t* bhp = &bh[nj >> 1][(nj & 1) * 2];
                    const uint32_t* blp = &bl[nj >> 1][(nj & 1) * 2];
                    mma_bf16(acc[mi][nj], ah[mi], bhp);
                    mma_bf16(acc[mi][nj], ah[mi], blp);
                    mma_bf16(acc[mi][nj], al[mi], bhp);
                }
        }
    };

    gload(0);
    sstore(0);
    __syncthreads();
    for (int c = 0; c < NCHUNK; c++) {
        if (c + 1 < NCHUNK) gload(c + 1);
        compute(c & 1);
        if (c + 1 < NCHUNK) {
            __syncthreads();
            sstore((c + 1) & 1);
            __syncthreads();
        }
    }

    const int r0 = lane >> 2, c0 = (lane & 3) * 2;
#pragma unroll
    for (int mi = 0; mi < 4; mi++) {
#pragma unroll
        for (int ro = 0; ro < 2; ro++) {
            const int m = m0 + wm + mi * 16 + r0 + ro * 8;
            if (mode == 0) {
                float* dst = outp + (size_t)m * EMBED + n0;
#pragma unroll
                for (int nj = 0; nj < 4; nj++) {
                    const int nl = wn + nj * 8 + c0;
                    float2 v;
                    v.x = acc[mi][nj][ro * 2 + 0] + __ldg(&bias[n0 + nl]);
                    v.y = acc[mi][nj][ro * 2 + 1] + __ldg(&bias[n0 + nl + 1]);
                    *(float2*)(dst + nl) = v;
                }
            } else {
                const int b = m >> 11, t = m & 2047;
                const size_t base = ((size_t)(b * NHEAD + head) * SEQ + t) * HDIM;
#pragma unroll
                for (int nj = 0; nj < 4; nj++) {
                    const int nl = wn + nj * 8 + c0;
                    float vx = (acc[mi][nj][ro * 2 + 0] + __ldg(&bias[n0 + nl])) * scale;
                    float vy = (acc[mi][nj][ro * 2 + 1] + __ldg(&bias[n0 + nl + 1])) * scale;
                    uint32_t h, l;
                    split_pack2(vx, vy, h, l);
                    *(uint32_t*)(outh + base + nl) = h;
                    *(uint32_t*)(outl + base + nl) = l;
                }
            }
        }
    }
}

__global__ __launch_bounds__(256, 1) void qkv_mma_kernel(
    const float* bq, const float* bk, const float* bv)
{
    const int z = blockIdx.z;
    const float* bias = (z == 0) ? bq : (z == 1) ? bk : bv;
    __nv_bfloat16* oh = (z == 0) ? g_Qh : (z == 1) ? g_Kh : g_Vh;
    __nv_bfloat16* ol = (z == 0) ? g_Ql : (z == 1) ? g_Kl : g_Vl;
    const float sc = (z == 0) ? kScale : 1.0f;
    mma_gemm_body(g_Xh, g_Xl, g_Wh[z], g_Wl[z], bias, nullptr, 1, blockIdx.x,
                  oh, ol, sc);
}

__global__ __launch_bounds__(256, 1) void o_mma_kernel(
    const float* bo, float* out)
{
    mma_gemm_body(g_Ah, g_Al, g_Wh[3], g_Wl[3], bo, out, 0, 0,
                  nullptr, nullptr, 1.0f);
}

// ---------------------------------------------------------------------------
// FA2 attention on tensor cores. 256 threads (8 warps), 128 q-rows per CTA,
// 64-key tiles, cp.async double-buffered K/V, hi/lo split throughout.
// Warp w owns q rows 16w..16w+15. Smem tiles: 256B pitch, XOR-swizzled.
// ---------------------------------------------------------------------------
#define KV_TILE_B  (64 * 256)          // 16 KB per 64x128 bf16 tile
#define AT_STAGE   (4 * KV_TILE_B)     // Kh, Kl, Vh, Vl
#define AT_SMEM    (2 * AT_STAGE)      // 128 KB
#define NKT        (SEQ / 64)          // 32

__global__ __launch_bounds__(256, 1) void attn_mma_kernel()
{
    extern __shared__ char smem[];
    const uint32_t sb = smem_u32(smem);
    const int tid = threadIdx.x, lane = tid & 31, wid = tid >> 5;
    const int bh = blockIdx.y;
    const int q0 = blockIdx.x * 128;
    const size_t bho = (size_t)bh * SEQ * HDIM;

    // ---- Load Q tile (hi at sb, lo at sb+32KB) and build A-fragments ----
    {
        const int row = tid >> 1;
        const char* gqh = (const char*)(g_Qh + bho + (size_t)(q0 + row) * HDIM);
        const char* gql = (const char*)(g_Ql + bho + (size_t)(q0 + row) * HDIM);
#pragma unroll
        for (int i = 0; i < 8; i++) {
            const uint32_t c = (tid & 1) * 8 + i;
            const uint32_t so = swz(row, c * 16);
            cp16(sb + so,         gqh + c * 16);
            cp16(sb + 32768 + so, gql + c * 16);
        }
        CP_COMMIT; CP_WAIT0;
        __syncthreads();
    }
    uint32_t qfh[8][4], qfl[8][4];
    {
        const uint32_t qrow = wid * 16 + (lane & 15);
#pragma unroll
        for (int ks = 0; ks < 8; ks++) {
            const uint32_t so = swz(qrow, ks * 32 + (lane >> 4) * 16);
            ldsm4(qfh[ks], sb + so);
            ldsm4(qfl[ks], sb + 32768 + so);
        }
    }
    __syncthreads();   // Q region about to be reused as K/V stage 0

    // ---- Online-softmax state + O accumulators ----
    float oacc[16][4];
#pragma unroll
    for (int j = 0; j < 16; j++)
#pragma unroll
        for (int r = 0; r < 4; r++) oacc[j][r] = 0.0f;
    float mrow[2] = {-1e30f, -1e30f}, lrow[2] = {0.0f, 0.0f};

    const char* gKh = (const char*)(g_Kh + bho);
    const char* gKl = (const char*)(g_Kl + bho);
    const char* gVh = (const char*)(g_Vh + bho);
    const char* gVl = (const char*)(g_Vl + bho);

    auto load_stage = [&](int stage, int kt) {
        const uint32_t s = sb + stage * AT_STAGE;
        const int row = tid >> 2;
        const size_t go = (size_t)(kt * 64 + row) * 256;   // bytes
#pragma unroll
        for (int i = 0; i < 4; i++) {
            const uint32_t c = (tid & 3) * 4 + i;
            const uint32_t so = swz(row, c * 16);
            cp16(s + so,                  gKh + go + c * 16);
            cp16(s + KV_TILE_B + so,      gKl + go + c * 16);
            cp16(s + 2 * KV_TILE_B + so,  gVh + go + c * 16);
            cp16(s + 3 * KV_TILE_B + so,  gVl + go + c * 16);
        }
    };

    load_stage(0, 0); CP_COMMIT;

    const uint32_t krow_off = (lane & 7) + ((lane >> 4) & 1) * 8;  // S-phase
    const uint32_t kb_off   = ((lane >> 3) & 1) * 16;
    const uint32_t vrow_off = (lane & 7) + ((lane >> 3) & 1) * 8;  // PV-phase
    const uint32_t vb_off   = ((lane >> 4) & 1) * 16;

    for (int kt = 0; kt < NKT; kt++) {
        if (kt + 1 < NKT) { load_stage((kt + 1) & 1, kt + 1); CP_COMMIT; CP_WAIT1; }
        else              { CP_WAIT0; }
        __syncthreads();

        const uint32_t s = sb + (kt & 1) * AT_STAGE;

        // ---- S = Q K^T (3-pass hi/lo), fp32 acc ----
        float sacc[8][4];
#pragma unroll
        for (int j = 0; j < 8; j++)
#pragma unroll
            for (int r = 0; r < 4; r++) sacc[j][r] = 0.0f;

#pragma unroll
        for (int ks = 0; ks < 8; ks++) {
            uint32_t kbh[4][4], kbl[4][4];
#pragma unroll
            for (int jp = 0; jp < 4; jp++) {
                const uint32_t so = swz(jp * 16 + krow_off, ks * 32 + kb_off);
                ldsm4(kbh[jp], s + so);
                ldsm4(kbl[jp], s + KV_TILE_B + so);
            }
#pragma unroll
            for (int jp = 0; jp < 4; jp++) {
                mma_bf16(sacc[2*jp],   qfh[ks], &kbh[jp][0]);
                mma_bf16(sacc[2*jp],   qfh[ks], &kbl[jp][0]);
                mma_bf16(sacc[2*jp],   qfl[ks], &kbh[jp][0]);
                mma_bf16(sacc[2*jp+1], qfh[ks], &kbh[jp][2]);
                mma_bf16(sacc[2*jp+1], qfh[ks], &kbl[jp][2]);
                mma_bf16(sacc[2*jp+1], qfl[ks], &kbh[jp][2]);
            }
        }

        // ---- Online softmax (rows lane>>2 and lane>>2+8) ----
#pragma unroll
        for (int rr = 0; rr < 2; rr++) {
            float mt = -1e30f;
#pragma unroll
            for (int j = 0; j < 8; j++)
                mt = fmaxf(mt, fmaxf(sacc[j][rr*2], sacc[j][rr*2+1]));
            mt = fmaxf(mt, __shfl_xor_sync(0xffffffffu, mt, 1));
            mt = fmaxf(mt, __shfl_xor_sync(0xffffffffu, mt, 2));
            const float mn = fmaxf(mrow[rr], mt);
            const float alpha = __expf(mrow[rr] - mn);
            float ls = 0.0f;
#pragma unroll
            for (int j = 0; j < 8; j++) {
                float p0 = __expf(sacc[j][rr*2]   - mn);
                float p1 = __expf(sacc[j][rr*2+1] - mn);
                sacc[j][rr*2] = p0; sacc[j][rr*2+1] = p1;
                ls += p0 + p1;
            }
            ls += __shfl_xor_sync(0xffffffffu, ls, 1);
            ls += __shfl_xor_sync(0xffffffffu, ls, 2);
            lrow[rr] = lrow[rr] * alpha + ls;
            mrow[rr] = mn;
#pragma unroll
            for (int j = 0; j < 16; j++) {
                oacc[j][rr*2]   *= alpha;
                oacc[j][rr*2+1] *= alpha;
            }
        }

        // ---- O += P V (3-pass hi/lo), P packed in-register from sacc ----
#pragma unroll
        for (int ks = 0; ks < 4; ks++) {
            uint32_t pah[4], pal[4];
#pragma unroll
            for (int half = 0; half < 2; half++) {
                const float* sc = sacc[2*ks + half];
                split_pack2(sc[0], sc[1], pah[2*half],   pal[2*half]);
                split_pack2(sc[2], sc[3], pah[2*half+1], pal[2*half+1]);
            }
#pragma unroll
            for (int jp = 0; jp < 8; jp++) {
                uint32_t vbh[4], vbl[4];
                const uint32_t so = swz(ks * 16 + vrow_off, jp * 32 + vb_off);
                ldsm4t(vbh, s + 2 * KV_TILE_B + so);
                ldsm4t(vbl, s + 3 * KV_TILE_B + so);
                mma_bf16(oacc[2*jp],   pah, &vbh[0]);
                mma_bf16(oacc[2*jp],   pah, &vbl[0]);
                mma_bf16(oacc[2*jp],   pal, &vbh[0]);
                mma_bf16(oacc[2*jp+1], pah, &vbh[2]);
                mma_bf16(oacc[2*jp+1], pah, &vbl[2]);
                mma_bf16(oacc[2*jp+1], pal, &vbh[2]);
            }
        }
        __syncthreads();
    }

    // ---- Epilogue: normalize, split hi/lo, write [b,t,h*128+hd] ----
    const int b_ = bh >> 4, h_ = bh & 15;
    const float inv0 = 1.0f / lrow[0], inv1 = 1.0f / lrow[1];
#pragma unroll
    for (int rr = 0; rr < 2; rr++) {
        const int t = q0 + wid * 16 + (lane >> 2) + rr * 8;
        const size_t base = ((size_t)(b_ * SEQ + t)) * EMBED + h_ * HDIM;
        const float inv = rr ? inv1 : inv0;
#pragma unroll
        for (int j = 0; j < 16; j++) {
            const int hd = j * 8 + (lane & 3) * 2;
            uint32_t h, l;
            split_pack2(oacc[j][rr*2] * inv, oacc[j][rr*2+1] * inv, h, l);
            *(uint32_t*)(g_Ah + base + hd) = h;
            *(uint32_t*)(g_Al + base + hd) = l;
        }
    }
}

// ---------------------------------------------------------------------------
// Launch sequence
// ---------------------------------------------------------------------------
extern "C" void kernel_launch(void* const* d_in, const int* in_sizes, int n_in,
                              void* d_out, int out_size)
{
    (void)in_sizes; (void)n_in; (void)out_size;
    const float* x  = (const float*)d_in[0];
    const float* wq = (const float*)d_in[1];
    const float* bq = (const float*)d_in[2];
    const float* wk = (const float*)d_in[3];
    const float* bk = (const float*)d_in[4];
    const float* wv = (const float*)d_in[5];
    const float* bv = (const float*)d_in[6];
    const float* wo = (const float*)d_in[7];
    const float* bo = (const float*)d_in[8];
    float* out = (float*)d_out;

    cudaFuncSetAttribute(qkv_mma_kernel,
                         cudaFuncAttributeMaxDynamicSharedMemorySize, GEMM_SMEM);
    cudaFuncSetAttribute(o_mma_kernel,
                         cudaFuncAttributeMaxDynamicSharedMemorySize, GEMM_SMEM);
    cudaFuncSetAttribute(attn_mma_kernel,
                         cudaFuncAttributeMaxDynamicSharedMemorySize, AT_SMEM);

    // 1. split x -> bf16 hi/lo
    split_kernel<<<(NTOK * EMBED / 4) / 256, 256>>>(x);
    // 2. transpose + split all four weight matrices
    wsplit_kernel<<<dim3(EMBED / 32, EMBED / 32, 4), dim3(32, 8)>>>(wq, wk, wv, wo);
    // 3. QKV projections -> bf16 hi/lo QKV (Q pre-scaled)
    qkv_mma_kernel<<<dim3(16, 32, 3), 256, GEMM_SMEM>>>(bq, bk, bv);
    // 4. tensor-core flash attention -> bf16 hi/lo A
    attn_mma_kernel<<<dim3(SEQ / 128, BATCH * NHEAD), 256, AT_SMEM>>>();
    // 5. output projection -> fp32 out
    o_mma_kernel<<<dim3(16, 32, 1), 256, GEMM_SMEM>>>(bo, out);
}